// round 11
// baseline (speedup 1.0000x reference)
#include <cuda_runtime.h>
#include <cstdint>
#include <math.h>

#define BB   8
#define CLEN 2048
#define QLEN 512
#define DD   1024
#define KTOT (4*DD)

// ---- scratch (static device globals; no allocation allowed) ----
__device__ float g_S[(size_t)BB*CLEN*QLEN];     // similarity / attention  [B,C,Q]
__device__ float g_M[BB*CLEN];                  // rowmax over Q
__device__ float g_Batt[BB*CLEN];               // softmax over C of rowmax
__device__ float g_C2Q[(size_t)BB*CLEN*DD];     // c2q attention output
__device__ float g_Q2Cpart[32*BB*DD];           // partial sums for q2c
__device__ float g_Q2C[BB*DD];                  // q2c attention output
__device__ float g_rowc[BB*CLEN];               // c@w_c + b_c
__device__ float g_rowq[BB*QLEN];               // q@w_q + b_q
__device__ float g_qT[(size_t)BB*DD*QLEN];      // q transposed [B, D, Q]

// ============================ helpers ============================
__device__ __forceinline__ float f2tf32(float x) {
    uint32_t t;
    asm("cvt.rna.tf32.f32 %0, %1;" : "=r"(t) : "f"(x));
    return __uint_as_float(t);
}

__device__ __forceinline__ void mma_tf32(float* d, const uint32_t* a, const uint32_t* b) {
    asm volatile(
        "mma.sync.aligned.m16n8k8.row.col.f32.tf32.tf32.f32 "
        "{%0,%1,%2,%3}, {%4,%5,%6,%7}, {%8,%9}, {%0,%1,%2,%3};"
        : "+f"(d[0]), "+f"(d[1]), "+f"(d[2]), "+f"(d[3])
        : "r"(a[0]), "r"(a[1]), "r"(a[2]), "r"(a[3]), "r"(b[0]), "r"(b[1]));
}

__device__ __forceinline__ uint32_t smem_u32(const void* p) {
    uint32_t a;
    asm("{ .reg .u64 t; cvta.to.shared.u64 t, %1; cvt.u32.u64 %0, t; }" : "=r"(a) : "l"(p));
    return a;
}
__device__ __forceinline__ void cp_async16(uint32_t dst, const void* src) {
    asm volatile("cp.async.cg.shared.global [%0], [%1], 16;" :: "r"(dst), "l"(src));
}
__device__ __forceinline__ void cp_commit() {
    asm volatile("cp.async.commit_group;");
}
__device__ __forceinline__ void cp_wait1() {
    asm volatile("cp.async.wait_group 1;" ::: "memory");
}

// ============================ global loaders ============================
// A tile: 128 rows (M) x 16 floats (K); thread loads rows ar, ar+64 at k offset ak
template<int MODE>
__device__ __forceinline__ void loadA_g(float4* v, const float* __restrict__ c,
                                        const float* __restrict__ w_cq,
                                        int b, int m0, int ar, int ak, int kt) {
    #pragma unroll
    for (int h = 0; h < 2; h++) {
        int r = ar + h * 64;
        int k = kt * 16 + ak;
        if (MODE == 1) {
            float4 t = *(const float4*)(c + ((size_t)(b * CLEN + m0 + r)) * DD + k);
            float4 w = *(const float4*)(w_cq + k);
            v[h] = make_float4(t.x * w.x, t.y * w.y, t.z * w.z, t.w * w.w);
        } else if (MODE == 2) {
            v[h] = *(const float4*)(g_S + ((size_t)(b * CLEN + m0 + r)) * QLEN + k);
        } else {
            int row = m0 + r;
            int seg = k >> 10;
            int kk  = k & 1023;
            if (seg == 0) {
                v[h] = *(const float4*)(c + (size_t)row * DD + kk);
            } else if (seg == 1) {
                v[h] = *(const float4*)(g_C2Q + (size_t)row * DD + kk);
            } else if (seg == 2) {
                float4 cv = *(const float4*)(c + (size_t)row * DD + kk);
                float4 av = *(const float4*)(g_C2Q + (size_t)row * DD + kk);
                v[h] = make_float4(cv.x * av.x, cv.y * av.y, cv.z * av.z, cv.w * av.w);
            } else {
                float4 cv = *(const float4*)(c + (size_t)row * DD + kk);
                float4 qv = *(const float4*)(g_Q2C + (size_t)b * DD + kk);
                v[h] = make_float4(cv.x * qv.x, cv.y * qv.y, cv.z * qv.z, cv.w * qv.w);
            }
        }
    }
}

// ============================ tensor-core GEMM (tf32 mma.sync) ============================
// CTA tile 128x256, 256 threads, 8 warps (2x4), warp tile 64x64, BK=16.
// A: register-prefetch + RNA tf32 + fragment-major smem (double buffer),
//    elem (r,k): idx = (((r>>4)*2+(k>>3))*32 + (r&7)*4 + ((k&3)^(r&3)))*4 + ((k>>2)&1)*2 + ((r>>3)&1)
// B: cp.async 16B direct staging, 3-stage ring, row stride 20 floats (conflict-free consumer).
//    raw fp32 in smem; tf32 MMA truncates B operand in hardware.
template<int MODE, int KTOTAL>
__global__ __launch_bounds__(256, 1)
void mma_gemm(const float* __restrict__ c, const float* __restrict__ q,
              const float* __restrict__ Wl, const float* __restrict__ w_cq,
              const float* __restrict__ b_cq, const float* __restrict__ b_l,
              float* __restrict__ outp) {
    __shared__ __align__(16) float As[2][2048];
    __shared__ __align__(16) float Bs[3][256 * 20];

    const int tid  = threadIdx.x;
    const int lane = tid & 31;
    const int wid  = tid >> 5;
    const int wm   = wid >> 2;        // 0..1  (64 M-rows each)
    const int wn   = wid & 3;         // 0..3  (64 N-cols each)

    int n0 = blockIdx.x * 256, m0, b;
    if (MODE == 3) { m0 = blockIdx.y * 128; b = m0 / CLEN; }
    else           { b = blockIdx.z; m0 = blockIdx.y * 128; }

    const int ar = tid >> 2;          // 0..63
    const int ak = (tid & 3) * 4;     // 0,4,8,12
    const int ck_p    = ak >> 3;
    const int chalf_p = (ak >> 2) & 1;

    // A producer bases (rows ar, ar+64)
    int aBase[2], xselA[2];
    #pragma unroll
    for (int h = 0; h < 2; h++) {
        int r = ar + h * 64;
        aBase[h] = (((r >> 4) * 2 + ck_p) * 32 + (r & 7) * 4) * 4 + chalf_p * 2 + ((r >> 3) & 1);
        xselA[h] = r & 3;
    }
    const int alane = (lane >> 2) * 4 + ((lane & 3) ^ ((lane >> 2) & 3));

    // B cp.async producer: rows tid>>2 + {0,64,128,192}, 16B chunk at kgroup = tid&3
    const int brow = tid >> 2;
    const int bkg  = tid & 3;
    const uint32_t BsAddr = smem_u32(&Bs[0][0]);

    // B global row base pointers
    const float* Bsrc;
    size_t bstride;
    if (MODE == 1)      { Bsrc = q    + ((size_t)(b * QLEN + n0)) * DD;   bstride = DD; }
    else if (MODE == 2) { Bsrc = g_qT + ((size_t)b * DD + n0) * QLEN;     bstride = QLEN; }
    else                { Bsrc = Wl   + (size_t)n0 * KTOT;                bstride = KTOT; }

    const int NT = KTOTAL / 16;

    auto issueB = [&](int it) {
        int stage = it - (it / 3) * 3;
        uint32_t sb = BsAddr + (uint32_t)stage * (256 * 20 * 4);
        int kofs = it * 16 + bkg * 4;
        #pragma unroll
        for (int h = 0; h < 4; h++) {
            int r = brow + h * 64;
            cp_async16(sb + (uint32_t)(r * 20 + bkg * 4) * 4, Bsrc + (size_t)r * bstride + kofs);
        }
        cp_commit();
    };

    float acc[4][8][4];
    #pragma unroll
    for (int i = 0; i < 4; i++)
        #pragma unroll
        for (int j = 0; j < 8; j++)
            #pragma unroll
            for (int l = 0; l < 4; l++) acc[i][j][l] = 0.f;

    float4 pa[2];
    issueB(0);
    issueB(1);
    loadA_g<MODE>(pa, c, w_cq, b, m0, ar, ak, 0);

    int p = 0;
    for (int it = 0; it < NT; it++) {
        // commit A tile (RNA tf32, fragment-major)
        #pragma unroll
        for (int h = 0; h < 2; h++) {
            float av[4] = {pa[h].x, pa[h].y, pa[h].z, pa[h].w};
            #pragma unroll
            for (int j = 0; j < 4; j++)
                As[p][aBase[h] + (j ^ xselA[h]) * 4] = f2tf32(av[j]);
        }
        cp_wait1();            // B(it) resident
        __syncthreads();

        if (it + 2 < NT) issueB(it + 2);
        if (it + 1 < NT) loadA_g<MODE>(pa, c, w_cq, b, m0, ar, ak, it + 1);

        const float* Bst = &Bs[it - (it / 3) * 3][0];

        #pragma unroll
        for (int ck = 0; ck < 2; ck++) {
            float4 a4[4];
            #pragma unroll
            for (int mt = 0; mt < 4; mt++)
                a4[mt] = *(const float4*)&As[p][(((wm * 4 + mt) * 2 + ck) * 32 + alane) * 4];
            uint32_t bf[8][2];
            #pragma unroll
            for (int nt = 0; nt < 8; nt++) {
                int nl = wn * 64 + nt * 8 + (lane >> 2);
                int ad = nl * 20 + ck * 8 + (lane & 3);
                bf[nt][0] = __float_as_uint(Bst[ad]);
                bf[nt][1] = __float_as_uint(Bst[ad + 4]);
            }
            #pragma unroll
            for (int mt = 0; mt < 4; mt++)
                #pragma unroll
                for (int nt = 0; nt < 8; nt++)
                    mma_tf32(acc[mt][nt], (const uint32_t*)&a4[mt], bf[nt]);
        }
        p ^= 1;
    }

    // ---- epilogue ----
    #pragma unroll
    for (int mt = 0; mt < 4; mt++) {
        int mloc0 = wm * 64 + mt * 16 + (lane >> 2);
        #pragma unroll
        for (int half = 0; half < 2; half++) {
            int mloc = mloc0 + half * 8;
            #pragma unroll
            for (int nt = 0; nt < 8; nt++) {
                float v0 = acc[mt][nt][half * 2 + 0];
                float v1 = acc[mt][nt][half * 2 + 1];
                int col = n0 + wn * 64 + nt * 8 + (lane & 3) * 2;
                if (MODE == 1) {
                    float rb = b_cq[0] + g_rowc[b * CLEN + m0 + mloc];
                    float2 o = make_float2(v0 + rb + g_rowq[b * QLEN + col],
                                           v1 + rb + g_rowq[b * QLEN + col + 1]);
                    *(float2*)(g_S + ((size_t)(b * CLEN + m0 + mloc)) * QLEN + col) = o;
                } else if (MODE == 2) {
                    *(float2*)(g_C2Q + ((size_t)(b * CLEN + m0 + mloc)) * DD + col) =
                        make_float2(v0, v1);
                } else {
                    float2 o = make_float2(v0 + b_l[col], v1 + b_l[col + 1]);
                    *(float2*)(outp + ((size_t)(m0 + mloc)) * DD + col) = o;
                }
            }
        }
    }
}

// ============================ small kernels ============================
__global__ void row_dot_kernel(const float* __restrict__ src, const float* __restrict__ w,
                               const float* __restrict__ bias, float* __restrict__ dst) {
    int row = blockIdx.x;
    const float* s = src + (size_t)row * DD;
    float acc = 0.f;
    for (int k = threadIdx.x; k < DD; k += 128) acc += s[k] * w[k];
    __shared__ float red[128];
    red[threadIdx.x] = acc; __syncthreads();
    for (int off = 64; off > 0; off >>= 1) {
        if (threadIdx.x < off) red[threadIdx.x] += red[threadIdx.x + off];
        __syncthreads();
    }
    if (threadIdx.x == 0) dst[row] = red[0] + bias[0];
}

__global__ void transpose_q_kernel(const float* __restrict__ q) {
    __shared__ float t[32][33];
    int b = blockIdx.z;
    int q0 = blockIdx.x * 32, d0 = blockIdx.y * 32;
    for (int i = threadIdx.y; i < 32; i += 8)
        t[i][threadIdx.x] = q[((size_t)b*QLEN + q0 + i)*DD + d0 + threadIdx.x];
    __syncthreads();
    for (int i = threadIdx.y; i < 32; i += 8)
        g_qT[((size_t)b*DD + d0 + i)*QLEN + q0 + threadIdx.x] = t[threadIdx.x][i];
}

__global__ void softmax_q_kernel() {
    int row = blockIdx.x;
    float* s = g_S + (size_t)row*QLEN;
    int t = threadIdx.x;
    float v[4];
    float m = -1e30f;
    #pragma unroll
    for (int i=0;i<4;i++){ v[i] = s[t + i*128]; m = fmaxf(m, v[i]); }
    __shared__ float red[128];
    red[t] = m; __syncthreads();
    for (int off=64; off>0; off>>=1){ if (t<off) red[t]=fmaxf(red[t],red[t+off]); __syncthreads(); }
    float rowmax = red[0];
    __syncthreads();
    float sum = 0.f;
    #pragma unroll
    for (int i=0;i<4;i++){ v[i] = __expf(v[i]-rowmax); sum += v[i]; }
    red[t]=sum; __syncthreads();
    for (int off=64; off>0; off>>=1){ if (t<off) red[t]+=red[t+off]; __syncthreads(); }
    float inv = 1.f/red[0];
    #pragma unroll
    for (int i=0;i<4;i++) s[t+i*128] = v[i]*inv;
    if (t==0) g_M[row]=rowmax;
}

__global__ void batt_kernel() {
    int b = blockIdx.x;
    int t = threadIdx.x;
    float v[8]; float m = -1e30f;
    #pragma unroll
    for (int i=0;i<8;i++){ v[i]=g_M[b*CLEN + t + i*256]; m=fmaxf(m,v[i]); }
    __shared__ float red[256];
    red[t]=m; __syncthreads();
    for (int off=128; off>0; off>>=1){ if (t<off) red[t]=fmaxf(red[t],red[t+off]); __syncthreads(); }
    float mx = red[0];
    __syncthreads();
    float sum = 0.f;
    #pragma unroll
    for (int i=0;i<8;i++){ v[i]=__expf(v[i]-mx); sum+=v[i]; }
    red[t]=sum; __syncthreads();
    for (int off=128; off>0; off>>=1){ if (t<off) red[t]+=red[t+off]; __syncthreads(); }
    float inv = 1.f/red[0];
    #pragma unroll
    for (int i=0;i<8;i++) g_Batt[b*CLEN + t + i*256] = v[i]*inv;
}

__global__ void q2c_part_kernel(const float* __restrict__ c) {
    int j = blockIdx.x;
    int b = blockIdx.y;
    int t = threadIdx.x;
    float acc[4] = {0.f,0.f,0.f,0.f};
    int cbase = j*64;
    const float* cb = c + ((size_t)b*CLEN + cbase)*DD;
    for (int cc=0; cc<64; cc++){
        float w = g_Batt[b*CLEN + cbase + cc];
        const float* row = cb + (size_t)cc*DD;
        #pragma unroll
        for (int i=0;i<4;i++) acc[i] += w * row[t + i*256];
    }
    #pragma unroll
    for (int i=0;i<4;i++) g_Q2Cpart[((size_t)j*BB + b)*DD + t + i*256] = acc[i];
}

__global__ void q2c_reduce_kernel() {
    int idx = blockIdx.x*256 + threadIdx.x;
    int b = idx / DD, d = idx % DD;
    float s = 0.f;
    for (int j=0;j<32;j++) s += g_Q2Cpart[((size_t)j*BB + b)*DD + d];
    g_Q2C[idx] = s;
}

// ============================ launch ============================
// Launch order is arranged so gemm1 is launch index 3 (the ncu-profiled slot).
extern "C" void kernel_launch(void* const* d_in, const int* in_sizes, int n_in,
                              void* d_out, int out_size) {
    const float* c    = (const float*)d_in[0];
    const float* q    = (const float*)d_in[1];
    const float* w_cq = (const float*)d_in[2];
    const float* b_cq = (const float*)d_in[3];
    const float* w_c  = (const float*)d_in[4];
    const float* b_c  = (const float*)d_in[5];
    const float* w_q  = (const float*)d_in[6];
    const float* b_q  = (const float*)d_in[7];
    const float* W_l  = (const float*)d_in[8];
    const float* b_l  = (const float*)d_in[9];
    float* out = (float*)d_out;

    float* d_rowc; cudaGetSymbolAddress((void**)&d_rowc, g_rowc);
    float* d_rowq; cudaGetSymbolAddress((void**)&d_rowq, g_rowq);

    row_dot_kernel<<<BB*CLEN, 128>>>(c, w_c, b_c, d_rowc);                     // 0
    row_dot_kernel<<<BB*QLEN, 128>>>(q, w_q, b_q, d_rowq);                     // 1
    transpose_q_kernel<<<dim3(QLEN/32, DD/32, BB), dim3(32, 8)>>>(q);          // 2

    mma_gemm<1, DD><<<dim3(QLEN/256, CLEN/128, BB), 256>>>(                    // 3 (profiled)
        c, q, W_l, w_cq, b_cq, b_l, out);

    softmax_q_kernel<<<BB*CLEN, 128>>>();                                      // 4
    batt_kernel<<<BB, 256>>>();                                                // 5
    q2c_part_kernel<<<dim3(32, BB), 256>>>(c);                                 // 6
    q2c_reduce_kernel<<<(BB*DD)/256, 256>>>();                                 // 7

    mma_gemm<2, QLEN><<<dim3(DD/256, CLEN/128, BB), 256>>>(                    // 8
        c, q, W_l, w_cq, b_cq, b_l, out);

    mma_gemm<3, KTOT><<<dim3(DD/256, (BB*CLEN)/128, 1), 256>>>(                // 9
        c, q, W_l, w_cq, b_cq, b_l, out);
}

// round 15
// speedup vs baseline: 1.3258x; 1.3258x over previous
#include <cuda_runtime.h>
#include <cuda_fp16.h>
#include <cstdint>
#include <math.h>

#define BB   8
#define CLEN 2048
#define QLEN 512
#define DD   1024
#define KTOT (4*DD)

// ---- scratch (static device globals; no allocation allowed) ----
__device__ float g_S[(size_t)BB*CLEN*QLEN];     // similarity / attention  [B,C,Q]
__device__ float g_M[BB*CLEN];                  // rowmax over Q
__device__ float g_Batt[BB*CLEN];               // softmax over C of rowmax
__device__ float g_C2Q[(size_t)BB*CLEN*DD];     // c2q attention output
__device__ float g_Q2Cpart[32*BB*DD];           // partial sums for q2c
__device__ float g_Q2C[BB*DD];                  // q2c attention output
__device__ float g_rowc[BB*CLEN];               // c@w_c + b_c
__device__ float g_rowq[BB*QLEN];               // q@w_q + b_q
__device__ float g_qT[(size_t)BB*DD*QLEN];      // q transposed [B, D, Q]

// ============================ helpers ============================
__device__ __forceinline__ uint32_t packh2(float lo, float hi) {
    __half2 h = __floats2half2_rn(lo, hi);     // x=lo (low 16), y=hi (high 16)
    return *reinterpret_cast<uint32_t*>(&h);
}

__device__ __forceinline__ void mma_f16(float* d, const uint32_t* a, const uint32_t* b) {
    asm volatile(
        "mma.sync.aligned.m16n8k16.row.col.f32.f16.f16.f32 "
        "{%0,%1,%2,%3}, {%4,%5,%6,%7}, {%8,%9}, {%0,%1,%2,%3};"
        : "+f"(d[0]), "+f"(d[1]), "+f"(d[2]), "+f"(d[3])
        : "r"(a[0]), "r"(a[1]), "r"(a[2]), "r"(a[3]), "r"(b[0]), "r"(b[1]));
}

// ============================ global loaders ============================
// A tile: 128 rows (M) x 16 floats (K); thread loads rows ar, ar+64 at k offset ak
template<int MODE>
__device__ __forceinline__ void loadA_g(float4* v, const float* __restrict__ c,
                                        const float* __restrict__ w_cq,
                                        int b, int m0, int ar, int ak, int kt) {
    #pragma unroll
    for (int h = 0; h < 2; h++) {
        int r = ar + h * 64;
        int k = kt * 16 + ak;
        if (MODE == 1) {
            float4 t = *(const float4*)(c + ((size_t)(b * CLEN + m0 + r)) * DD + k);
            float4 w = *(const float4*)(w_cq + k);
            v[h] = make_float4(t.x * w.x, t.y * w.y, t.z * w.z, t.w * w.w);
        } else if (MODE == 2) {
            v[h] = *(const float4*)(g_S + ((size_t)(b * CLEN + m0 + r)) * QLEN + k);
        } else {
            int row = m0 + r;
            int seg = k >> 10;
            int kk  = k & 1023;
            if (seg == 0) {
                v[h] = *(const float4*)(c + (size_t)row * DD + kk);
            } else if (seg == 1) {
                v[h] = *(const float4*)(g_C2Q + (size_t)row * DD + kk);
            } else if (seg == 2) {
                float4 cv = *(const float4*)(c + (size_t)row * DD + kk);
                float4 av = *(const float4*)(g_C2Q + (size_t)row * DD + kk);
                v[h] = make_float4(cv.x * av.x, cv.y * av.y, cv.z * av.z, cv.w * av.w);
            } else {
                float4 cv = *(const float4*)(c + (size_t)row * DD + kk);
                float4 qv = *(const float4*)(g_Q2C + (size_t)b * DD + kk);
                v[h] = make_float4(cv.x * qv.x, cv.y * qv.y, cv.z * qv.z, cv.w * qv.w);
            }
        }
    }
}

// B tile: 256 rows (N) x 16 floats (K); thread loads rows br, br+64, br+128, br+192
template<int MODE>
__device__ __forceinline__ void loadB_g(float4* v, const float* __restrict__ q,
                                        const float* __restrict__ Wl,
                                        int b, int n0, int br, int ak, int kt) {
    #pragma unroll
    for (int h = 0; h < 4; h++) {
        int r = br + h * 64;
        int k = kt * 16 + ak;
        if (MODE == 1) {
            v[h] = *(const float4*)(q + ((size_t)(b * QLEN + n0 + r)) * DD + k);
        } else if (MODE == 2) {
            v[h] = *(const float4*)(g_qT + ((size_t)b * DD + n0 + r) * QLEN + k);
        } else {
            v[h] = *(const float4*)(Wl + (size_t)(n0 + r) * KTOT + k);
        }
    }
}

// ============================ tensor-core GEMM (fp16 mma.sync m16n8k16) ============================
// CTA tile 128x256, 256 threads, 8 warps (2x4), warp tile 64x64, BK=16, double-buffered.
// Storage unit = fp16x2 pair (uint32), pair index k2 = k>>1 (0..7 per tile).
// A pair (r,k2): word = ((r>>4)*32 + (r&7)*4)*4 + ((r>>3)&1)  +  ((k2&3)^(r&3))*4 + (k2>>2)*2
// B pair (n,k2): word = ((n>>3)*32 + (n&7)*4)*2               +  ((k2&3)^(n&3))*2 + (k2>>2)
// Consumer: A fragment = one LDS.128 (uint4), B fragment = one LDS.64 (uint2); conflict-free.
// fp32 accumulate; fp16 significand == tf32 significand, so accuracy matches the tf32 path.
template<int MODE, int KTOTAL>
__global__ __launch_bounds__(256, 1)
void mma_gemm(const float* __restrict__ c, const float* __restrict__ q,
              const float* __restrict__ Wl, const float* __restrict__ w_cq,
              const float* __restrict__ b_cq, const float* __restrict__ b_l,
              float* __restrict__ outp) {
    __shared__ __align__(16) uint32_t As[2][1024];   // 128 x 16 fp16  (4 KB/stage)
    __shared__ __align__(16) uint32_t Bs[2][2048];   // 256 x 16 fp16  (8 KB/stage)

    const int tid  = threadIdx.x;
    const int lane = tid & 31;
    const int wid  = tid >> 5;
    const int wm   = wid >> 2;        // 0..1  (64 M-rows each)
    const int wn   = wid & 3;         // 0..3  (64 N-cols each)

    int n0 = blockIdx.x * 256, m0, b;
    if (MODE == 3) { m0 = blockIdx.y * 128; b = m0 / CLEN; }
    else           { b = blockIdx.z; m0 = blockIdx.y * 128; }

    const int ar = tid >> 2;          // 0..63
    const int ak = (tid & 3) * 4;     // 0,4,8,12 -> pairs k2 = ak/2, ak/2+1
    const int k2a = ak >> 1;

    // producer bases: A rows {ar, ar+64}; B rows {ar, ar+64, ar+128, ar+192}
    int aBase[2], xselA[2];
    int bBase[4], xselB[4];
    #pragma unroll
    for (int h = 0; h < 2; h++) {
        int r = ar + h * 64;
        aBase[h] = ((r >> 4) * 32 + (r & 7) * 4) * 4 + ((r >> 3) & 1);
        xselA[h] = r & 3;
    }
    #pragma unroll
    for (int h = 0; h < 4; h++) {
        int r = ar + h * 64;
        bBase[h] = ((r >> 3) * 32 + (r & 7) * 4) * 2;
        xselB[h] = r & 3;
    }
    const int alane = (lane >> 2) * 4 + ((lane & 3) ^ ((lane >> 2) & 3));

    float acc[4][8][4];
    #pragma unroll
    for (int i = 0; i < 4; i++)
        #pragma unroll
        for (int j = 0; j < 8; j++)
            #pragma unroll
            for (int l = 0; l < 4; l++) acc[i][j][l] = 0.f;

    const int NT = KTOTAL / 16;
    float4 pa[2], pb[4];
    loadA_g<MODE>(pa, c, w_cq, b, m0, ar, ak, 0);
    loadB_g<MODE>(pb, q, Wl, b, n0, ar, ak, 0);

    int p = 0;
    for (int kt = 0; kt < NT; kt++) {
        // commit prefetched tile to smem as fp16 pairs
        #pragma unroll
        for (int h = 0; h < 2; h++) {
            uint32_t p0 = packh2(pa[h].x, pa[h].y);      // pair k2a
            uint32_t p1 = packh2(pa[h].z, pa[h].w);      // pair k2a+1
            As[p][aBase[h] + (( k2a      & 3) ^ xselA[h]) * 4 + (( k2a      >> 2) * 2)] = p0;
            As[p][aBase[h] + (((k2a + 1) & 3) ^ xselA[h]) * 4 + (((k2a + 1) >> 2) * 2)] = p1;
        }
        #pragma unroll
        for (int h = 0; h < 4; h++) {
            uint32_t p0 = packh2(pb[h].x, pb[h].y);
            uint32_t p1 = packh2(pb[h].z, pb[h].w);
            Bs[p][bBase[h] + (( k2a      & 3) ^ xselB[h]) * 2 + ( k2a      >> 2)] = p0;
            Bs[p][bBase[h] + (((k2a + 1) & 3) ^ xselB[h]) * 2 + ((k2a + 1) >> 2)] = p1;
        }
        __syncthreads();

        if (kt + 1 < NT) {
            loadA_g<MODE>(pa, c, w_cq, b, m0, ar, ak, kt + 1);
            loadB_g<MODE>(pb, q, Wl, b, n0, ar, ak, kt + 1);
        }

        // compute: one k16 step; 4 LDS.128 (A) + 8 LDS.64 (B) + 32 MMA per warp
        uint4 a4[4];
        uint2 b2[8];
        #pragma unroll
        for (int mt = 0; mt < 4; mt++)
            a4[mt] = *(const uint4*)&As[p][((wm * 4 + mt) * 32 + alane) * 4];
        #pragma unroll
        for (int nt = 0; nt < 8; nt++)
            b2[nt] = *(const uint2*)&Bs[p][((wn * 8 + nt) * 32 + alane) * 2];
        #pragma unroll
        for (int mt = 0; mt < 4; mt++)
            #pragma unroll
            for (int nt = 0; nt < 8; nt++)
                mma_f16(acc[mt][nt], &a4[mt].x, &b2[nt].x);
        p ^= 1;
    }

    // ---- epilogue ----
    #pragma unroll
    for (int mt = 0; mt < 4; mt++) {
        int mloc0 = wm * 64 + mt * 16 + (lane >> 2);
        #pragma unroll
        for (int half = 0; half < 2; half++) {
            int mloc = mloc0 + half * 8;
            #pragma unroll
            for (int nt = 0; nt < 8; nt++) {
                float v0 = acc[mt][nt][half * 2 + 0];
                float v1 = acc[mt][nt][half * 2 + 1];
                int col = n0 + wn * 64 + nt * 8 + (lane & 3) * 2;
                if (MODE == 1) {
                    float rb = b_cq[0] + g_rowc[b * CLEN + m0 + mloc];
                    float2 o = make_float2(v0 + rb + g_rowq[b * QLEN + col],
                                           v1 + rb + g_rowq[b * QLEN + col + 1]);
                    *(float2*)(g_S + ((size_t)(b * CLEN + m0 + mloc)) * QLEN + col) = o;
                } else if (MODE == 2) {
                    *(float2*)(g_C2Q + ((size_t)(b * CLEN + m0 + mloc)) * DD + col) =
                        make_float2(v0, v1);
                } else {
                    float2 o = make_float2(v0 + b_l[col], v1 + b_l[col + 1]);
                    *(float2*)(outp + ((size_t)(m0 + mloc)) * DD + col) = o;
                }
            }
        }
    }
}

// ============================ small kernels ============================
__global__ void row_dot_kernel(const float* __restrict__ src, const float* __restrict__ w,
                               const float* __restrict__ bias, float* __restrict__ dst) {
    int row = blockIdx.x;
    const float* s = src + (size_t)row * DD;
    float acc = 0.f;
    for (int k = threadIdx.x; k < DD; k += 128) acc += s[k] * w[k];
    __shared__ float red[128];
    red[threadIdx.x] = acc; __syncthreads();
    for (int off = 64; off > 0; off >>= 1) {
        if (threadIdx.x < off) red[threadIdx.x] += red[threadIdx.x + off];
        __syncthreads();
    }
    if (threadIdx.x == 0) dst[row] = red[0] + bias[0];
}

__global__ void transpose_q_kernel(const float* __restrict__ q) {
    __shared__ float t[32][33];
    int b = blockIdx.z;
    int q0 = blockIdx.x * 32, d0 = blockIdx.y * 32;
    for (int i = threadIdx.y; i < 32; i += 8)
        t[i][threadIdx.x] = q[((size_t)b*QLEN + q0 + i)*DD + d0 + threadIdx.x];
    __syncthreads();
    for (int i = threadIdx.y; i < 32; i += 8)
        g_qT[((size_t)b*DD + d0 + i)*QLEN + q0 + threadIdx.x] = t[threadIdx.x][i];
}

__global__ void softmax_q_kernel() {
    int row = blockIdx.x;
    float* s = g_S + (size_t)row*QLEN;
    int t = threadIdx.x;
    float v[4];
    float m = -1e30f;
    #pragma unroll
    for (int i=0;i<4;i++){ v[i] = s[t + i*128]; m = fmaxf(m, v[i]); }
    __shared__ float red[128];
    red[t] = m; __syncthreads();
    for (int off=64; off>0; off>>=1){ if (t<off) red[t]=fmaxf(red[t],red[t+off]); __syncthreads(); }
    float rowmax = red[0];
    __syncthreads();
    float sum = 0.f;
    #pragma unroll
    for (int i=0;i<4;i++){ v[i] = __expf(v[i]-rowmax); sum += v[i]; }
    red[t]=sum; __syncthreads();
    for (int off=64; off>0; off>>=1){ if (t<off) red[t]+=red[t+off]; __syncthreads(); }
    float inv = 1.f/red[0];
    #pragma unroll
    for (int i=0;i<4;i++) s[t+i*128] = v[i]*inv;
    if (t==0) g_M[row]=rowmax;
}

__global__ void batt_kernel() {
    int b = blockIdx.x;
    int t = threadIdx.x;
    float v[8]; float m = -1e30f;
    #pragma unroll
    for (int i=0;i<8;i++){ v[i]=g_M[b*CLEN + t + i*256]; m=fmaxf(m,v[i]); }
    __shared__ float red[256];
    red[t]=m; __syncthreads();
    for (int off=128; off>0; off>>=1){ if (t<off) red[t]=fmaxf(red[t],red[t+off]); __syncthreads(); }
    float mx = red[0];
    __syncthreads();
    float sum = 0.f;
    #pragma unroll
    for (int i=0;i<8;i++){ v[i]=__expf(v[i]-mx); sum+=v[i]; }
    red[t]=sum; __syncthreads();
    for (int off=128; off>0; off>>=1){ if (t<off) red[t]+=red[t+off]; __syncthreads(); }
    float inv = 1.f/red[0];
    #pragma unroll
    for (int i=0;i<8;i++) g_Batt[b*CLEN + t + i*256] = v[i]*inv;
}

__global__ void q2c_part_kernel(const float* __restrict__ c) {
    int j = blockIdx.x;
    int b = blockIdx.y;
    int t = threadIdx.x;
    float acc[4] = {0.f,0.f,0.f,0.f};
    int cbase = j*64;
    const float* cb = c + ((size_t)b*CLEN + cbase)*DD;
    for (int cc=0; cc<64; cc++){
        float w = g_Batt[b*CLEN + cbase + cc];
        const float* row = cb + (size_t)cc*DD;
        #pragma unroll
        for (int i=0;i<4;i++) acc[i] += w * row[t + i*256];
    }
    #pragma unroll
    for (int i=0;i<4;i++) g_Q2Cpart[((size_t)j*BB + b)*DD + t + i*256] = acc[i];
}

__global__ void q2c_reduce_kernel() {
    int idx = blockIdx.x*256 + threadIdx.x;
    int b = idx / DD, d = idx % DD;
    float s = 0.f;
    for (int j=0;j<32;j++) s += g_Q2Cpart[((size_t)j*BB + b)*DD + d];
    g_Q2C[idx] = s;
}

// ============================ launch ============================
// Launch order keeps gemm1 at launch index 3 (the ncu-profiled slot).
extern "C" void kernel_launch(void* const* d_in, const int* in_sizes, int n_in,
                              void* d_out, int out_size) {
    const float* c    = (const float*)d_in[0];
    const float* q    = (const float*)d_in[1];
    const float* w_cq = (const float*)d_in[2];
    const float* b_cq = (const float*)d_in[3];
    const float* w_c  = (const float*)d_in[4];
    const float* b_c  = (const float*)d_in[5];
    const float* w_q  = (const float*)d_in[6];
    const float* b_q  = (const float*)d_in[7];
    const float* W_l  = (const float*)d_in[8];
    const float* b_l  = (const float*)d_in[9];
    float* out = (float*)d_out;

    float* d_rowc; cudaGetSymbolAddress((void**)&d_rowc, g_rowc);
    float* d_rowq; cudaGetSymbolAddress((void**)&d_rowq, g_rowq);

    row_dot_kernel<<<BB*CLEN, 128>>>(c, w_c, b_c, d_rowc);                     // 0
    row_dot_kernel<<<BB*QLEN, 128>>>(q, w_q, b_q, d_rowq);                     // 1
    transpose_q_kernel<<<dim3(QLEN/32, DD/32, BB), dim3(32, 8)>>>(q);          // 2

    mma_gemm<1, DD><<<dim3(QLEN/256, CLEN/128, BB), 256>>>(                    // 3 (profiled)
        c, q, W_l, w_cq, b_cq, b_l, out);

    softmax_q_kernel<<<BB*CLEN, 128>>>();                                      // 4
    batt_kernel<<<BB, 256>>>();                                                // 5
    q2c_part_kernel<<<dim3(32, BB), 256>>>(c);                                 // 6
    q2c_reduce_kernel<<<(BB*DD)/256, 256>>>();                                 // 7

    mma_gemm<2, QLEN><<<dim3(DD/256, CLEN/128, BB), 256>>>(                    // 8
        c, q, W_l, w_cq, b_cq, b_l, out);

    mma_gemm<3, KTOT><<<dim3(DD/256, (BB*CLEN)/128, 1), 256>>>(                // 9
        c, q, W_l, w_cq, b_cq, b_l, out);
}

// round 16
// speedup vs baseline: 2.0215x; 1.5247x over previous
#include <cuda_runtime.h>
#include <cuda_fp16.h>
#include <cstdint>
#include <math.h>

#define BB   8
#define CLEN 2048
#define QLEN 512
#define DD   1024
#define KTOT (4*DD)

// ---- fp32 scratch ----
__device__ float g_S[(size_t)BB*CLEN*QLEN];     // gemm1 out (softmax input)
__device__ float g_M[BB*CLEN];
__device__ float g_Batt[BB*CLEN];
__device__ float g_Q2Cpart[32*BB*DD];
__device__ float g_Q2C[BB*DD];
__device__ float g_rowc[BB*CLEN];
__device__ float g_rowq[BB*QLEN];

// ---- fp16 operand buffers ----
__device__ __half g_ch  [(size_t)BB*CLEN*DD];   // half(c)
__device__ __half g_cwh [(size_t)BB*CLEN*DD];   // half(c*w_cq)
__device__ __half g_qh  [(size_t)BB*QLEN*DD];   // half(q)
__device__ __half g_qTh [(size_t)BB*DD*QLEN];   // half(q^T)
__device__ __half g_Wh  [(size_t)DD*KTOT];      // half(W_l)
__device__ __half g_Sh  [(size_t)BB*CLEN*QLEN]; // half(softmax(S))
__device__ __half g_C2Qh[(size_t)BB*CLEN*DD];   // half(c2q)
__device__ __half g_x2h [(size_t)BB*CLEN*DD];   // half(c*c2q)
__device__ __half g_x3h [(size_t)BB*CLEN*DD];   // half(c*q2c)

// ============================ helpers ============================
__device__ __forceinline__ uint32_t packh2(float lo, float hi) {
    __half2 h = __floats2half2_rn(lo, hi);
    return *reinterpret_cast<uint32_t*>(&h);
}
__device__ __forceinline__ void mma_f16(float* d, const uint32_t* a, const uint32_t* b) {
    asm volatile(
        "mma.sync.aligned.m16n8k16.row.col.f32.f16.f16.f32 "
        "{%0,%1,%2,%3}, {%4,%5,%6,%7}, {%8,%9}, {%0,%1,%2,%3};"
        : "+f"(d[0]), "+f"(d[1]), "+f"(d[2]), "+f"(d[3])
        : "r"(a[0]), "r"(a[1]), "r"(a[2]), "r"(a[3]), "r"(b[0]), "r"(b[1]));
}
__device__ __forceinline__ uint32_t smem_u32(const void* p) {
    uint32_t a;
    asm("{ .reg .u64 t; cvta.to.shared.u64 t, %1; cvt.u32.u64 %0, t; }" : "=r"(a) : "l"(p));
    return a;
}
__device__ __forceinline__ void cp_async16(uint32_t dst, const void* src) {
    asm volatile("cp.async.cg.shared.global [%0], [%1], 16;" :: "r"(dst), "l"(src));
}
__device__ __forceinline__ void cp_commit() {
    asm volatile("cp.async.commit_group;");
}
template<int N>
__device__ __forceinline__ void cp_wait() {
    asm volatile("cp.async.wait_group %0;" :: "n"(N) : "memory");
}
__device__ __forceinline__ void ldsm4(uint32_t& r0, uint32_t& r1, uint32_t& r2, uint32_t& r3,
                                      uint32_t a) {
    asm volatile("ldmatrix.sync.aligned.m8n8.x4.shared.b16 {%0,%1,%2,%3}, [%4];"
                 : "=r"(r0), "=r"(r1), "=r"(r2), "=r"(r3) : "r"(a));
}

// ============================ GEMM (fp16 mma.sync, cp.async pipeline) ============================
// CTA tile 128x256, 256 threads, 8 warps (2x4), warp tile 64x64, BK=64, 3-stage cp.async.
// smem per stage: A 128x128B (16KB) + B 256x128B (32KB). Rows = 8 chunks of 16B,
// swizzle: phys_chunk = chunk ^ (row & 7) -> ldmatrix conflict-free.
// MODE 1: S  = cwh @ qh^T   (+bias epilogue, fp32 out)            K=DD
// MODE 2: c2q = Sh @ qTh^T  (epilogue -> C2Qh, x2h fp16)          K=QLEN
// MODE 3: out = [ch|C2Qh|x2h|x3h] @ Wh^T + b_l                    K=4*DD
static const int GSMEM = 3 * 16384 + 3 * 32768;   // 147456 bytes

template<int MODE, int KTOTAL>
__global__ __launch_bounds__(256)
void mma_gemm(const float* __restrict__ c, const float* __restrict__ b_cq,
              const float* __restrict__ b_l, float* __restrict__ outp) {
    extern __shared__ __align__(16) char dynsmem[];
    const uint32_t sb = smem_u32(dynsmem);
    constexpr int NT = KTOTAL / 64;
    constexpr uint32_t ASTG = 16384, BSTG = 32768, BOFF = 3 * ASTG;

    const int tid  = threadIdx.x;
    const int lane = tid & 31;
    const int wid  = tid >> 5;
    const int wm   = wid >> 2;
    const int wn   = wid & 3;

    int n0 = blockIdx.x * 256, m0, b;
    if (MODE == 3) { m0 = blockIdx.y * 128; b = m0 / CLEN; }
    else           { b = blockIdx.z; m0 = blockIdx.y * 128; }

    const __half* Ap = nullptr; const __half* Bp; int astr, bstr;
    if (MODE == 1) {
        Ap = g_cwh + (size_t)(b * CLEN + m0) * DD;  astr = DD;
        Bp = g_qh  + (size_t)(b * QLEN + n0) * DD;  bstr = DD;
    } else if (MODE == 2) {
        Ap = g_Sh  + (size_t)(b * CLEN + m0) * QLEN; astr = QLEN;
        Bp = g_qTh + (size_t)(b * DD + n0) * QLEN;   bstr = QLEN;
    } else {
        astr = DD;
        Bp = g_Wh + (size_t)n0 * KTOT;               bstr = KTOT;
    }

    // producer mapping: A row = tid>>1 (0..127), chunks (tid&1)*4 + 0..3; B rows +0,+128
    const int prow = tid >> 1;
    const int pchb = (tid & 1) * 4;

    auto issue = [&](int t) {
        if (t < NT) {
            int k0 = t * 64;
            int st = t - (t / 3) * 3;
            uint32_t as = sb + (uint32_t)st * ASTG;
            uint32_t bs = sb + BOFF + (uint32_t)st * BSTG;
            const __half* asrc;
            if (MODE == 3) {
                int seg = k0 >> 10, kk = k0 & 1023;
                const __half* sp = (seg == 0) ? g_ch : (seg == 1) ? g_C2Qh
                                 : (seg == 2) ? g_x2h : g_x3h;
                asrc = sp + (size_t)m0 * DD + kk;
            } else {
                asrc = Ap + k0;
            }
            #pragma unroll
            for (int j = 0; j < 4; j++) {
                int ch = pchb + j;
                cp_async16(as + (uint32_t)(prow * 128 + ((ch ^ (prow & 7)) << 4)),
                           asrc + (size_t)prow * astr + ch * 8);
            }
            #pragma unroll
            for (int h = 0; h < 2; h++) {
                int r = prow + h * 128;
                #pragma unroll
                for (int j = 0; j < 4; j++) {
                    int ch = pchb + j;
                    cp_async16(bs + (uint32_t)(r * 128 + ((ch ^ (r & 7)) << 4)),
                               Bp + k0 + (size_t)r * bstr + ch * 8);
                }
            }
        }
        cp_commit();
    };

    float acc[4][8][4];
    #pragma unroll
    for (int i = 0; i < 4; i++)
        #pragma unroll
        for (int j = 0; j < 8; j++)
            #pragma unroll
            for (int l = 0; l < 4; l++) acc[i][j][l] = 0.f;

    issue(0);
    issue(1);

    const uint32_t aRowOff = (uint32_t)((wm * 64 + (lane & 15)) * 128);
    const uint32_t bRowOff = (uint32_t)((wn * 64 + (lane & 15)) * 128);
    const int lhi = lane >> 4, l7 = lane & 7;

    for (int t = 0; t < NT; t++) {
        cp_wait<1>();          // tile t resident
        __syncthreads();
        issue(t + 2);          // into buffer freed at t-1 (safe after this sync)

        int st = t - (t / 3) * 3;
        uint32_t as = sb + (uint32_t)st * ASTG + aRowOff;
        uint32_t bs = sb + BOFF + (uint32_t)st * BSTG + bRowOff;

        #pragma unroll
        for (int ks = 0; ks < 4; ks++) {
            uint32_t co = (uint32_t)(((ks * 2 + lhi) ^ l7) << 4);
            uint4 afr[4];
            uint32_t bfr[4][4];
            #pragma unroll
            for (int mt = 0; mt < 4; mt++)
                ldsm4(afr[mt].x, afr[mt].y, afr[mt].z, afr[mt].w,
                      as + (uint32_t)(mt * 16 * 128) + co);
            #pragma unroll
            for (int ntp = 0; ntp < 4; ntp++)
                ldsm4(bfr[ntp][0], bfr[ntp][1], bfr[ntp][2], bfr[ntp][3],
                      bs + (uint32_t)(ntp * 16 * 128) + co);
            #pragma unroll
            for (int mt = 0; mt < 4; mt++)
                #pragma unroll
                for (int ntp = 0; ntp < 4; ntp++) {
                    uint32_t b0[2] = {bfr[ntp][0], bfr[ntp][2]};
                    uint32_t b1[2] = {bfr[ntp][1], bfr[ntp][3]};
                    mma_f16(acc[mt][2 * ntp],     &afr[mt].x, b0);
                    mma_f16(acc[mt][2 * ntp + 1], &afr[mt].x, b1);
                }
        }
    }

    // ---- epilogue ----
    #pragma unroll
    for (int mt = 0; mt < 4; mt++) {
        int mloc0 = wm * 64 + mt * 16 + (lane >> 2);
        #pragma unroll
        for (int half = 0; half < 2; half++) {
            int mloc = mloc0 + half * 8;
            #pragma unroll
            for (int nt = 0; nt < 8; nt++) {
                float v0 = acc[mt][nt][half * 2 + 0];
                float v1 = acc[mt][nt][half * 2 + 1];
                int col = n0 + wn * 64 + nt * 8 + (lane & 3) * 2;
                if (MODE == 1) {
                    float rb = b_cq[0] + g_rowc[b * CLEN + m0 + mloc];
                    float2 o = make_float2(v0 + rb + g_rowq[b * QLEN + col],
                                           v1 + rb + g_rowq[b * QLEN + col + 1]);
                    *(float2*)(g_S + ((size_t)(b * CLEN + m0 + mloc)) * QLEN + col) = o;
                } else if (MODE == 2) {
                    size_t row = (size_t)(b * CLEN + m0 + mloc);
                    float2 cv = *(const float2*)(c + row * DD + col);
                    *(uint32_t*)(g_C2Qh + row * DD + col) = packh2(v0, v1);
                    *(uint32_t*)(g_x2h  + row * DD + col) = packh2(v0 * cv.x, v1 * cv.y);
                } else {
                    float2 o = make_float2(v0 + b_l[col], v1 + b_l[col + 1]);
                    *(float2*)(outp + ((size_t)(m0 + mloc)) * DD + col) = o;
                }
            }
        }
    }
}

// ============================ prep: fp32 -> fp16 conversions ============================
// blocks [0, NCB): c -> ch, cwh ; [NCB, NCB+NWB): W_l -> Wh ; rest: q -> qh + qTh (transpose)
__global__ void prep_kernel(const float* __restrict__ c, const float* __restrict__ q,
                            const float* __restrict__ Wl, const float* __restrict__ w_cq) {
    __shared__ float tile[32][33];
    const int NCB = (BB * CLEN * DD) / 2048;   // 8192
    const int NWB = (DD * KTOT) / 2048;        // 2048
    int blk = blockIdx.x, tid = threadIdx.x;
    if (blk < NCB) {
        size_t idx = ((size_t)blk * 256 + tid) * 8;
        int k = (int)(idx & (DD - 1));
        float4 v1 = *(const float4*)(c + idx), v2 = *(const float4*)(c + idx + 4);
        float4 w1 = *(const float4*)(w_cq + k), w2 = *(const float4*)(w_cq + k + 4);
        uint32_t* dc = (uint32_t*)(g_ch + idx);
        dc[0] = packh2(v1.x, v1.y); dc[1] = packh2(v1.z, v1.w);
        dc[2] = packh2(v2.x, v2.y); dc[3] = packh2(v2.z, v2.w);
        uint32_t* dw = (uint32_t*)(g_cwh + idx);
        dw[0] = packh2(v1.x * w1.x, v1.y * w1.y); dw[1] = packh2(v1.z * w1.z, v1.w * w1.w);
        dw[2] = packh2(v2.x * w2.x, v2.y * w2.y); dw[3] = packh2(v2.z * w2.z, v2.w * w2.w);
    } else if (blk < NCB + NWB) {
        size_t idx = ((size_t)(blk - NCB) * 256 + tid) * 8;
        float4 v1 = *(const float4*)(Wl + idx), v2 = *(const float4*)(Wl + idx + 4);
        uint32_t* dw = (uint32_t*)(g_Wh + idx);
        dw[0] = packh2(v1.x, v1.y); dw[1] = packh2(v1.z, v1.w);
        dw[2] = packh2(v2.x, v2.y); dw[3] = packh2(v2.z, v2.w);
    } else {
        int t = blk - NCB - NWB;          // 0..4095
        int b = t >> 9;
        int rem = t & 511;
        int q0 = (rem & 15) * 32;
        int d0 = (rem >> 4) * 32;
        int tx = tid & 31, ty = tid >> 5;
        for (int i = ty; i < 32; i += 8) {
            float v = q[((size_t)b * QLEN + q0 + i) * DD + d0 + tx];
            tile[i][tx] = v;
            g_qh[((size_t)b * QLEN + q0 + i) * DD + d0 + tx] = __float2half_rn(v);
        }
        __syncthreads();
        for (int i = ty; i < 32; i += 8)
            g_qTh[((size_t)b * DD + d0 + i) * QLEN + q0 + tx] = __float2half_rn(tile[tx][i]);
    }
}

// ============================ small kernels ============================
__global__ void row_dot_kernel(const float* __restrict__ src, const float* __restrict__ w,
                               const float* __restrict__ bias, float* __restrict__ dst) {
    int row = blockIdx.x;
    const float* s = src + (size_t)row * DD;
    float acc = 0.f;
    for (int k = threadIdx.x; k < DD; k += 128) acc += s[k] * w[k];
    __shared__ float red[128];
    red[threadIdx.x] = acc; __syncthreads();
    for (int off = 64; off > 0; off >>= 1) {
        if (threadIdx.x < off) red[threadIdx.x] += red[threadIdx.x + off];
        __syncthreads();
    }
    if (threadIdx.x == 0) dst[row] = red[0] + bias[0];
}

__global__ void softmax_q_kernel() {
    int row = blockIdx.x;
    const float* s = g_S + (size_t)row * QLEN;
    __half* sh = g_Sh + (size_t)row * QLEN;
    int t = threadIdx.x;
    float v[4];
    float m = -1e30f;
    #pragma unroll
    for (int i = 0; i < 4; i++) { v[i] = s[t + i * 128]; m = fmaxf(m, v[i]); }
    __shared__ float red[128];
    red[t] = m; __syncthreads();
    for (int off = 64; off > 0; off >>= 1) { if (t < off) red[t] = fmaxf(red[t], red[t + off]); __syncthreads(); }
    float rowmax = red[0];
    __syncthreads();
    float sum = 0.f;
    #pragma unroll
    for (int i = 0; i < 4; i++) { v[i] = __expf(v[i] - rowmax); sum += v[i]; }
    red[t] = sum; __syncthreads();
    for (int off = 64; off > 0; off >>= 1) { if (t < off) red[t] += red[t + off]; __syncthreads(); }
    float inv = 1.f / red[0];
    #pragma unroll
    for (int i = 0; i < 4; i++) sh[t + i * 128] = __float2half_rn(v[i] * inv);
    if (t == 0) g_M[row] = rowmax;
}

__global__ void batt_kernel() {
    int b = blockIdx.x;
    int t = threadIdx.x;
    float v[8]; float m = -1e30f;
    #pragma unroll
    for (int i = 0; i < 8; i++) { v[i] = g_M[b * CLEN + t + i * 256]; m = fmaxf(m, v[i]); }
    __shared__ float red[256];
    red[t] = m; __syncthreads();
    for (int off = 128; off > 0; off >>= 1) { if (t < off) red[t] = fmaxf(red[t], red[t + off]); __syncthreads(); }
    float mx = red[0];
    __syncthreads();
    float sum = 0.f;
    #pragma unroll
    for (int i = 0; i < 8; i++) { v[i] = __expf(v[i] - mx); sum += v[i]; }
    red[t] = sum; __syncthreads();
    for (int off = 128; off > 0; off >>= 1) { if (t < off) red[t] += red[t + off]; __syncthreads(); }
    float inv = 1.f / red[0];
    #pragma unroll
    for (int i = 0; i < 8; i++) g_Batt[b * CLEN + t + i * 256] = v[i] * inv;
}

__global__ void q2c_part_kernel(const float* __restrict__ c) {
    int j = blockIdx.x;
    int b = blockIdx.y;
    int t = threadIdx.x;
    float acc[4] = {0.f, 0.f, 0.f, 0.f};
    int cbase = j * 64;
    const float* cb = c + ((size_t)b * CLEN + cbase) * DD;
    for (int cc = 0; cc < 64; cc++) {
        float w = g_Batt[b * CLEN + cbase + cc];
        const float* row = cb + (size_t)cc * DD;
        #pragma unroll
        for (int i = 0; i < 4; i++) acc[i] += w * row[t + i * 256];
    }
    #pragma unroll
    for (int i = 0; i < 4; i++) g_Q2Cpart[((size_t)j * BB + b) * DD + t + i * 256] = acc[i];
}

__global__ void q2c_reduce_kernel() {
    int idx = blockIdx.x * 256 + threadIdx.x;
    int b = idx / DD, d = idx % DD;
    float s = 0.f;
    for (int j = 0; j < 32; j++) s += g_Q2Cpart[((size_t)j * BB + b) * DD + d];
    g_Q2C[idx] = s;
}

// x3h = half(c * q2c[b])
__global__ void x3_kernel(const float* __restrict__ c) {
    size_t idx = ((size_t)blockIdx.x * 256 + threadIdx.x) * 8;
    int b = (int)(idx / ((size_t)CLEN * DD));
    int k = (int)(idx & (DD - 1));
    float4 c1 = *(const float4*)(c + idx), c2 = *(const float4*)(c + idx + 4);
    float4 q1 = *(const float4*)(g_Q2C + b * DD + k);
    float4 q2 = *(const float4*)(g_Q2C + b * DD + k + 4);
    uint32_t* d = (uint32_t*)(g_x3h + idx);
    d[0] = packh2(c1.x * q1.x, c1.y * q1.y);
    d[1] = packh2(c1.z * q1.z, c1.w * q1.w);
    d[2] = packh2(c2.x * q2.x, c2.y * q2.y);
    d[3] = packh2(c2.z * q2.z, c2.w * q2.w);
}

// ============================ launch ============================
// Order keeps gemm1 at launch index 3 (the ncu-profiled slot).
extern "C" void kernel_launch(void* const* d_in, const int* in_sizes, int n_in,
                              void* d_out, int out_size) {
    const float* c    = (const float*)d_in[0];
    const float* q    = (const float*)d_in[1];
    const float* w_cq = (const float*)d_in[2];
    const float* b_cq = (const float*)d_in[3];
    const float* w_c  = (const float*)d_in[4];
    const float* b_c  = (const float*)d_in[5];
    const float* w_q  = (const float*)d_in[6];
    const float* b_q  = (const float*)d_in[7];
    const float* W_l  = (const float*)d_in[8];
    const float* b_l  = (const float*)d_in[9];
    float* out = (float*)d_out;

    float* d_rowc; cudaGetSymbolAddress((void**)&d_rowc, g_rowc);
    float* d_rowq; cudaGetSymbolAddress((void**)&d_rowq, g_rowq);

    cudaFuncSetAttribute(mma_gemm<1, DD>,   cudaFuncAttributeMaxDynamicSharedMemorySize, GSMEM);
    cudaFuncSetAttribute(mma_gemm<2, QLEN>, cudaFuncAttributeMaxDynamicSharedMemorySize, GSMEM);
    cudaFuncSetAttribute(mma_gemm<3, KTOT>, cudaFuncAttributeMaxDynamicSharedMemorySize, GSMEM);

    const int PREP_BLOCKS = (BB*CLEN*DD)/2048 + (DD*KTOT)/2048 + BB*16*32;  // 14336

    row_dot_kernel<<<BB*CLEN, 128>>>(c, w_c, b_c, d_rowc);                   // 0
    row_dot_kernel<<<BB*QLEN, 128>>>(q, w_q, b_q, d_rowq);                   // 1
    prep_kernel<<<PREP_BLOCKS, 256>>>(c, q, W_l, w_cq);                      // 2

    mma_gemm<1, DD><<<dim3(QLEN/256, CLEN/128, BB), 256, GSMEM>>>(           // 3 (profiled)
        c, b_cq, b_l, out);

    softmax_q_kernel<<<BB*CLEN, 128>>>();                                    // 4
    batt_kernel<<<BB, 256>>>();                                              // 5
    q2c_part_kernel<<<dim3(32, BB), 256>>>(c);                               // 6
    q2c_reduce_kernel<<<(BB*DD)/256, 256>>>();                               // 7
    x3_kernel<<<(BB*CLEN*DD)/2048, 256>>>(c);                                // 8

    mma_gemm<2, QLEN><<<dim3(DD/256, CLEN/128, BB), 256, GSMEM>>>(           // 9
        c, b_cq, b_l, out);

    mma_gemm<3, KTOT><<<dim3(DD/256, (BB*CLEN)/128, 1), 256, GSMEM>>>(       // 10
        c, b_cq, b_l, out);
}